// round 17
// baseline (speedup 1.0000x reference)
#include <cuda_runtime.h>
#include <cuda_bf16.h>
#include <cstdint>

// out[b,s] = | prod_k cos((x[b,k]-sv[s,k])/2) |  =  | P12 * P34 |
// P12 = 1/2 [ cos((u+ - v+)/2) + cos((u- - v-)/2) ],  u± = x0±x1, v± = s0±s1
// -> each P is a 4-term dot product of row features vs col features (1/2
//    folded into the row side).
//
// R17: fully warp-decoupled. No __syncthreads anywhere.
//  - warp tile = 8 rows x 128 cols; block = 8 warps (64 x 128), grid 2048.
//  - B (col) features: computed PER-LANE (16 sincos) straight into the 8
//    packed registers -- no smem, no barrier, no hoist LDS.
//  - A (row) features: warp-private smem fill (1 sincos/lane) + __syncwarp.
#define NB 4096
#define NS 4096

__device__ __forceinline__ uint64_t pk2(float lo, float hi) {
    uint64_t r; asm("mov.b64 %0, {%1, %2};" : "=l"(r) : "f"(lo), "f"(hi)); return r;
}
__device__ __forceinline__ uint64_t mul2(uint64_t a, uint64_t b) {
    uint64_t r; asm("mul.rn.f32x2 %0, %1, %2;" : "=l"(r) : "l"(a), "l"(b)); return r;
}
__device__ __forceinline__ uint64_t fma2(uint64_t a, uint64_t b, uint64_t c) {
    uint64_t r; asm("fma.rn.f32x2 %0, %1, %2, %3;" : "=l"(r) : "l"(a), "l"(b), "l"(c)); return r;
}
__device__ __forceinline__ uint64_t abs2(uint64_t v) {
    asm("and.b64 %0, %0, 0x7FFFFFFF7FFFFFFF;" : "+l"(v)); return v;
}
__device__ __forceinline__ uint64_t dup2(float v) {
    uint64_t r; asm("mov.b64 %0, {%1, %1};" : "=l"(r) : "f"(v)); return r;
}

__global__ __launch_bounds__(256, 4) void qk_warp_kernel(
    const float* __restrict__ x,
    const float* __restrict__ sv,
    float* __restrict__ out)
{
    // A (row) features, un-dup'd: per row 8 floats
    // {c+12, s+12, c-12, s-12, c+34, s+34, c-34, s-34}, 1/2 folded in.
    // Each warp touches only its own 8-row slice.
    __shared__ __align__(16) float sxf[64 * 8];    // 2 KB

    const int b0   = blockIdx.y << 6;    // 64 rows per block
    const int s0   = blockIdx.x << 7;    // 128 cols per block
    const int t    = threadIdx.x;
    const int w    = t >> 5;             // warp id: rows b0 + 8w .. +7
    const int lane = t & 31;             // 4 cols at s0 + 4*lane

    // ---- A fill: warp-private, 1 sincos/lane, __syncwarp only ----
    {
        // lane = r*4 + k: element k of local row r (coalesced 128B per warp)
        float v = x[(b0 + (w << 3)) * 4 + lane];
        float p = __shfl_xor_sync(0xFFFFFFFFu, v, 1);     // pair partner
        const int g = lane & 3;
        float u = (g & 1) ? (p - v) : (v + p);            // even: sum, odd: diff
        float sn, cs;
        __sincosf(u * 0.5f, &sn, &cs);
        cs *= 0.5f; sn *= 0.5f;                           // fold the 1/2 per pair
        const int row = (w << 3) + (lane >> 2);
        sxf[(row << 3) + (g << 1) + 0] = cs;
        sxf[(row << 3) + (g << 1) + 1] = sn;
    }

    // ---- B features: per-lane, straight into packed registers ----
    // B[f].x packs cols (0,1), B[f].y packs cols (2,3); f order:
    // {C+12, S+12, C-12, S-12, C+34, S+34, C-34, S-34}
    ulonglong2 B[8];
    {
        float4 v0 = *reinterpret_cast<const float4*>(&sv[(size_t)(s0 + (lane << 2) + 0) * 4]);
        float4 v1 = *reinterpret_cast<const float4*>(&sv[(size_t)(s0 + (lane << 2) + 1) * 4]);
        float4 v2 = *reinterpret_cast<const float4*>(&sv[(size_t)(s0 + (lane << 2) + 2) * 4]);
        float4 v3 = *reinterpret_cast<const float4*>(&sv[(size_t)(s0 + (lane << 2) + 3) * 4]);

        float c0, s0f, c1, s1f, c2, s2f, c3, s3f;
        // +12: (x0+x1)/2
        __sincosf((v0.x + v0.y) * 0.5f, &s0f, &c0);
        __sincosf((v1.x + v1.y) * 0.5f, &s1f, &c1);
        __sincosf((v2.x + v2.y) * 0.5f, &s2f, &c2);
        __sincosf((v3.x + v3.y) * 0.5f, &s3f, &c3);
        B[0].x = pk2(c0, c1);  B[0].y = pk2(c2, c3);
        B[1].x = pk2(s0f, s1f); B[1].y = pk2(s2f, s3f);
        // -12: (x0-x1)/2
        __sincosf((v0.x - v0.y) * 0.5f, &s0f, &c0);
        __sincosf((v1.x - v1.y) * 0.5f, &s1f, &c1);
        __sincosf((v2.x - v2.y) * 0.5f, &s2f, &c2);
        __sincosf((v3.x - v3.y) * 0.5f, &s3f, &c3);
        B[2].x = pk2(c0, c1);  B[2].y = pk2(c2, c3);
        B[3].x = pk2(s0f, s1f); B[3].y = pk2(s2f, s3f);
        // +34: (x2+x3)/2
        __sincosf((v0.z + v0.w) * 0.5f, &s0f, &c0);
        __sincosf((v1.z + v1.w) * 0.5f, &s1f, &c1);
        __sincosf((v2.z + v2.w) * 0.5f, &s2f, &c2);
        __sincosf((v3.z + v3.w) * 0.5f, &s3f, &c3);
        B[4].x = pk2(c0, c1);  B[4].y = pk2(c2, c3);
        B[5].x = pk2(s0f, s1f); B[5].y = pk2(s2f, s3f);
        // -34: (x2-x3)/2
        __sincosf((v0.z - v0.w) * 0.5f, &s0f, &c0);
        __sincosf((v1.z - v1.w) * 0.5f, &s1f, &c1);
        __sincosf((v2.z - v2.w) * 0.5f, &s2f, &c2);
        __sincosf((v3.z - v3.w) * 0.5f, &s3f, &c3);
        B[6].x = pk2(c0, c1);  B[6].y = pk2(c2, c3);
        B[7].x = pk2(s0f, s1f); B[7].y = pk2(s2f, s3f);
    }

    __syncwarp();   // A slice visible to the whole warp

    float* orow = out + (size_t)(b0 + (w << 3)) * NS + (s0 + (lane << 2));

#pragma unroll 4
    for (int i = 0; i < 8; i++) {
        // 2 warp-broadcast LDS.128 per row
        const float4* arec = reinterpret_cast<const float4*>(
            &sxf[(((w << 3) + i) << 3)]);
        float4 h0 = arec[0];   // c+12, s+12, c-12, s-12
        float4 h1 = arec[1];   // c+34, s+34, c-34, s-34

        uint64_t cp = dup2(h0.x), sp = dup2(h0.y);
        uint64_t cm = dup2(h0.z), sm = dup2(h0.w);

        uint64_t p12a = fma2(sm, B[3].x, fma2(cm, B[2].x,
                        fma2(sp, B[1].x, mul2(cp, B[0].x))));
        uint64_t p12b = fma2(sm, B[3].y, fma2(cm, B[2].y,
                        fma2(sp, B[1].y, mul2(cp, B[0].y))));

        cp = dup2(h1.x); sp = dup2(h1.y);
        cm = dup2(h1.z); sm = dup2(h1.w);

        uint64_t p34a = fma2(sm, B[7].x, fma2(cm, B[6].x,
                        fma2(sp, B[5].x, mul2(cp, B[4].x))));
        uint64_t p34b = fma2(sm, B[7].y, fma2(cm, B[6].y,
                        fma2(sp, B[5].y, mul2(cp, B[4].y))));

        ulonglong2 o;
        o.x = abs2(mul2(p12a, p34a));   // (out0, out1)
        o.y = abs2(mul2(p12b, p34b));   // (out2, out3)
        *reinterpret_cast<ulonglong2*>(orow + (size_t)i * NS) = o;  // STG.128
    }
}

extern "C" void kernel_launch(void* const* d_in, const int* in_sizes, int n_in,
                              void* d_out, int out_size) {
    const float* x  = (const float*)d_in[0];
    const float* sv = (const float*)d_in[1];
    float* out = (float*)d_out;

    dim3 grid(NS / 128, NB / 64);   // 32 x 64 = 2048 blocks
    qk_warp_kernel<<<grid, 256>>>(x, sv, out);
}